// round 4
// baseline (speedup 1.0000x reference)
#include <cuda_runtime.h>

#define BT     4096      // B*T
#define KCAND  64
#define DK     128
#define DCTX   256
#define DV     128
#define GAMMA  1.0f
#define ETA    1.0f
#define INV_TEMP 1.0f

#define CHUNK   8        // candidates per pipeline stage
#define NCHUNK  8        // KCAND / CHUNK
#define STAGE_F 5120     // floats per stage: K 1024 + ctx 2048 + rel 1024 + ent 1024
#define SMEM_FLOATS (2*STAGE_F + KCAND*DV + DK + DCTX + KCAND + 4*KCAND)
#define SMEM_BYTES  (SMEM_FLOATS * 4)   // 76544 B -> 3 blocks/SM

// 4 MB scratch for Qw = Q @ W_ctx (device global => allowed, no allocation)
__device__ float g_qw[BT * DCTX];

#define CP_ASYNC_CG16(dst, src) \
    asm volatile("cp.async.cg.shared.global [%0], [%1], 16;\n" :: "r"(dst), "l"(src))
#define CP_ASYNC_COMMIT() asm volatile("cp.async.commit_group;\n" ::)
#define CP_ASYNC_WAIT(N)  asm volatile("cp.async.wait_group %0;\n" :: "n"(N))

__device__ __forceinline__ unsigned smem_u32(const void* p) {
    return (unsigned)__cvta_generic_to_shared(p);
}

// ---------------------------------------------------------------------------
// Kernel 1: Qw[row, c] = sum_d Q[row, d] * W_ctx[d, c]
// 8 rows/block, grid 512. float4 W loads: 1 LDG.128 + 2 LDS per 8 FMA.
// ---------------------------------------------------------------------------
__global__ __launch_bounds__(256) void qw_kernel(const float* __restrict__ Q,
                                                 const float* __restrict__ W) {
    __shared__ float qsh[8][DK];
    const int tid = threadIdx.x;
    const int rowbase = blockIdx.x * 8;
    for (int i = tid; i < 8 * DK; i += 256)
        qsh[i >> 7][i & 127] = Q[rowbase * DK + i];
    __syncthreads();

    const int cg = tid & 63;   // float4 column group (4 cols)
    const int rg = tid >> 6;   // 0..3 -> rows rg*2, rg*2+1
    const int r0 = rg * 2, r1 = r0 + 1;
    float4 a0 = make_float4(0.f, 0.f, 0.f, 0.f);
    float4 a1 = a0;
    const float4* W4 = (const float4*)W;   // [128][64] float4

#pragma unroll 4
    for (int d = 0; d < DK; ++d) {
        const float4 wv = W4[d * 64 + cg];       // coalesced, L1/L2-hot
        const float q0 = qsh[r0][d];             // broadcast LDS
        const float q1 = qsh[r1][d];
        a0.x = fmaf(q0, wv.x, a0.x); a0.y = fmaf(q0, wv.y, a0.y);
        a0.z = fmaf(q0, wv.z, a0.z); a0.w = fmaf(q0, wv.w, a0.w);
        a1.x = fmaf(q1, wv.x, a1.x); a1.y = fmaf(q1, wv.y, a1.y);
        a1.z = fmaf(q1, wv.z, a1.z); a1.w = fmaf(q1, wv.w, a1.w);
    }
    float4* out4 = (float4*)g_qw;   // [BT][64] float4
    out4[(rowbase + r0) * 64 + cg] = a0;
    out4[(rowbase + r1) * 64 + cg] = a1;
}

// ---------------------------------------------------------------------------
// Kernel 2: one block per (b,t) row. All bulk operands streamed via cp.async
// into a double-buffered smem pipeline; compute is smem + shuffles only.
// ---------------------------------------------------------------------------
__global__ __launch_bounds__(256) void kb_main_kernel(
    const float* __restrict__ Q,
    const float* __restrict__ K_kb,
    const float* __restrict__ V_kb,
    const float* __restrict__ ctx,
    const float* __restrict__ b_ctx,
    const float* __restrict__ rel_emb,
    const float* __restrict__ ent_emb,
    const float* __restrict__ q_min,
    const float* __restrict__ q_max,
    const float* __restrict__ tau_min,
    const float* __restrict__ tau_max,
    const int*   __restrict__ rel_id,
    const int*   __restrict__ ent_id,
    float* __restrict__ out_alpha,
    float* __restrict__ out_v)
{
    extern __shared__ float smem[];
    float* sA    = smem;                         // [2][STAGE_F] stages
    float* sV    = smem + 2 * STAGE_F;           // [64][128]
    float* sQ    = sV + KCAND * DV;              // 128
    float* sQW   = sQ + DK;                      // 256
    float* sS    = sQW + DCTX;                   // 64 scores -> alpha
    int*   sRid  = (int*)(sS + KCAND);           // 64
    int*   sEid  = sRid + KCAND;                 // 64
    float* sTmin = (float*)(sEid + KCAND);       // 64
    float* sTmax = sTmin + KCAND;                // 64

    const int row  = blockIdx.x;
    const int tid  = threadIdx.x;
    const int warp = tid >> 5;
    const int lane = tid & 31;

    const long base_k = (long)row * KCAND * DK;
    const long base_c = (long)row * KCAND * DCTX;

    // ---- prologue: small per-row data (LDG + STS, drained by barrier) ----
    if (tid < 64)        sRid [tid]       = rel_id [row * KCAND + tid];
    else if (tid < 128)  sEid [tid - 64]  = ent_id [row * KCAND + tid - 64];
    else if (tid < 192)  sTmin[tid - 128] = tau_min[row * KCAND + tid - 128];
    else                 sTmax[tid - 192] = tau_max[row * KCAND + tid - 192];
    if (tid < DK) sQ[tid] = Q[(long)row * DK + tid];
    sQW[tid] = g_qw[(long)row * DCTX + tid];
    __syncthreads();    // ids visible for cp.async address generation

    // ---- chunk issuer: K+ctx+rel+ent stage (20KB) + V slice (4KB), 1 group
    auto issue_chunk = [&](int c, int stg) {
        const int kc = c * CHUNK;
        const unsigned dst = smem_u32(sA + stg * STAGE_F);
        // j0: K      f4 idx [0,256)
        { const int cand = tid >> 5, off = tid & 31;
          CP_ASYNC_CG16(dst + tid * 16,
                        K_kb + base_k + (long)(kc + cand) * DK + off * 4); }
        // j1,j2: ctx f4 idx [256,768)
        { const int cand = tid >> 6, off = tid & 63;
          CP_ASYNC_CG16(dst + (256 + tid) * 16,
                        ctx + base_c + (long)(kc + cand) * DCTX + off * 4); }
        { const int t = tid + 256; const int cand = t >> 6, off = t & 63;
          CP_ASYNC_CG16(dst + (256 + t) * 16,
                        ctx + base_c + (long)(kc + cand) * DCTX + off * 4); }
        // j3: rel    f4 idx [768,1024)
        { const int cand = tid >> 5, off = tid & 31;
          CP_ASYNC_CG16(dst + (768 + tid) * 16,
                        rel_emb + (long)sRid[kc + cand] * DK + off * 4); }
        // j4: ent    f4 idx [1024,1280)
        { const int cand = tid >> 5, off = tid & 31;
          CP_ASYNC_CG16(dst + (1024 + tid) * 16,
                        ent_emb + (long)sEid[kc + cand] * DK + off * 4); }
        // V slice: rows kc..kc+7
        { const int cand = tid >> 5, off = tid & 31;
          CP_ASYNC_CG16(smem_u32(sV + (kc + cand) * DV + off * 4),
                        V_kb + base_k + (long)(kc + cand) * DV + off * 4); }
        CP_ASYNC_COMMIT();
    };

    issue_chunk(0, 0);
    issue_chunk(1, 1);

    // qb = Q . b_ctx (overlaps in-flight copies)
    const float4 qv  = ((const float4*)sQ)[lane];
    const float4 bv  = ((const float4*)b_ctx)[lane];
    float qb = qv.x * bv.x + qv.y * bv.y + qv.z * bv.z + qv.w * bv.w;
#pragma unroll
    for (int off = 16; off; off >>= 1) qb += __shfl_xor_sync(~0u, qb, off);

    const float qmn = q_min[row];
    const float qmx = q_max[row];
    const float inv_sqrt = 0.08838834764831843f; // 1/sqrt(128)
    const float4 qwa = ((const float4*)sQW)[lane];
    const float4 qwb = ((const float4*)sQW)[lane + 32];

#pragma unroll
    for (int c = 0; c < NCHUNK; ++c) {
        if (c < NCHUNK - 1) { CP_ASYNC_WAIT(1); } else { CP_ASYNC_WAIT(0); }
        __syncthreads();    // chunk c data visible to all threads

        const float* S = sA + (c & 1) * STAGE_F;
        const int k = c * CHUNK + warp;   // this warp's candidate

        const float4 kv = ((const float4*)S)[warp * 32 + lane];
        const float4 c0 = ((const float4*)(S + 1024))[warp * 64 + lane];
        const float4 c1 = ((const float4*)(S + 1024))[warp * 64 + lane + 32];
        const float4 rv = ((const float4*)(S + 3072))[warp * 32 + lane];
        const float4 ev = ((const float4*)(S + 4096))[warp * 32 + lane];

        float sem = qv.x * kv.x + qv.y * kv.y + qv.z * kv.z + qv.w * kv.w;
        float cx  = qv.x * (rv.x + ev.x) + qv.y * (rv.y + ev.y)
                  + qv.z * (rv.z + ev.z) + qv.w * (rv.w + ev.w);
        cx += qwa.x * c0.x + qwa.y * c0.y + qwa.z * c0.z + qwa.w * c0.w;
        cx += qwb.x * c1.x + qwb.y * c1.y + qwb.z * c1.z + qwb.w * c1.w;

        float tot = sem + GAMMA * cx;
#pragma unroll
        for (int off = 16; off; off >>= 1) tot += __shfl_xor_sync(~0u, tot, off);

        if (lane == 0) {
            const float tmin = sTmin[k];
            const float tmax = sTmax[k];
            const float inter = fmaxf(fminf(qmx, tmax) - fmaxf(qmn, tmin), 0.f);
            const float uni   = fmaxf(qmx, tmax) - fminf(qmn, tmin);
            const float ts    = inter / (uni + 1e-6f);
            sS[k] = (tot + GAMMA * qb) * inv_sqrt + ETA * ts;
        }
        __syncthreads();    // compute done before buffer reuse
        if (c + 2 < NCHUNK) issue_chunk(c + 2, c & 1);
    }

    // Softmax over 64 scores (warp 0)
    if (warp == 0) {
        float s0 = sS[lane], s1 = sS[lane + 32];
        float m = fmaxf(s0, s1);
#pragma unroll
        for (int off = 16; off; off >>= 1) m = fmaxf(m, __shfl_xor_sync(~0u, m, off));
        float e0 = __expf((s0 - m) * INV_TEMP);
        float e1 = __expf((s1 - m) * INV_TEMP);
        float sum = e0 + e1;
#pragma unroll
        for (int off = 16; off; off >>= 1) sum += __shfl_xor_sync(~0u, sum, off);
        const float inv = 1.0f / sum;
        const float a0 = e0 * inv, a1 = e1 * inv;
        sS[lane]      = a0;
        sS[lane + 32] = a1;
        out_alpha[row * KCAND + lane]      = a0;
        out_alpha[row * KCAND + lane + 32] = a1;
    }
    __syncthreads();

    // V_tilde = sum_k alpha[k] * V[k,:] from smem — split k across 2 groups
    const int g = tid >> 7;
    const int d = tid & 127;
    const float* vs = sV + g * 32 * DV;
    float acc = 0.f;
#pragma unroll
    for (int kk = 0; kk < 32; ++kk)
        acc = fmaf(sS[g * 32 + kk], vs[kk * DV + d], acc);
    float* sVp = sQW;   // reuse (qw already consumed into registers)
    if (g) sVp[d] = acc;
    __syncthreads();
    if (!g) out_v[(long)row * DV + d] = acc + sVp[d];
}

// ---------------------------------------------------------------------------
extern "C" void kernel_launch(void* const* d_in, const int* in_sizes, int n_in,
                              void* d_out, int out_size) {
    const float* Q     = (const float*)d_in[0];
    const float* K_kb  = (const float*)d_in[1];
    const float* V_kb  = (const float*)d_in[2];
    const float* ctx   = (const float*)d_in[3];
    const float* W     = (const float*)d_in[4];
    const float* b_ctx = (const float*)d_in[5];
    const float* rel   = (const float*)d_in[6];
    const float* ent   = (const float*)d_in[7];
    const float* qmin  = (const float*)d_in[8];
    const float* qmax  = (const float*)d_in[9];
    const float* tmin  = (const float*)d_in[10];
    const float* tmax  = (const float*)d_in[11];
    const int*   rid   = (const int*)d_in[12];
    const int*   eid   = (const int*)d_in[13];

    float* out       = (float*)d_out;
    float* out_alpha = out;                    // [BT, 64]
    float* out_v     = out + BT * KCAND;       // [BT, 128]

    static int configured = 0;
    if (!configured) {
        cudaFuncSetAttribute(kb_main_kernel,
                             cudaFuncAttributeMaxDynamicSharedMemorySize,
                             SMEM_BYTES);
        configured = 1;
    }

    qw_kernel<<<BT / 8, 256>>>(Q, W);
    kb_main_kernel<<<BT, 256, SMEM_BYTES>>>(Q, K_kb, V_kb, ctx, b_ctx, rel, ent,
                                            qmin, qmax, tmin, tmax, rid, eid,
                                            out_alpha, out_v);
}

// round 5
// speedup vs baseline: 1.0474x; 1.0474x over previous
#include <cuda_runtime.h>

#define BT     4096      // B*T
#define KCAND  64
#define DK     128
#define DCTX   256
#define DV     128
#define GAMMA  1.0f
#define ETA    1.0f
#define INV_TEMP 1.0f

#define CHUNK   8        // candidates per pipeline stage
#define NCHUNK  8        // KCAND / CHUNK
#define STAGE_F 5120     // floats per stage: K 1024 + ctx 2048 + rel 1024 + ent 1024
#define SMEM_FLOATS (2*STAGE_F + KCAND*DV + DK + DCTX + KCAND + 4*KCAND)
#define SMEM_BYTES  (SMEM_FLOATS * 4)   // 76544 B

#define CP_ASYNC_CG16(dst, src) \
    asm volatile("cp.async.cg.shared.global [%0], [%1], 16;\n" :: "r"(dst), "l"(src))
#define CP_ASYNC_COMMIT() asm volatile("cp.async.commit_group;\n" ::)
#define CP_ASYNC_WAIT(N)  asm volatile("cp.async.wait_group %0;\n" :: "n"(N))

__device__ __forceinline__ unsigned smem_u32(const void* p) {
    return (unsigned)__cvta_generic_to_shared(p);
}

// ---------------------------------------------------------------------------
// Single fused kernel: one block per (b,t) row.
//  - prologue: cp.async chunks 0/1 in flight while the block computes its own
//    Qw = Q_row @ W_ctx from L2-hot W (replaces the separate qw kernel)
//  - 8-chunk double-buffered score pipeline, V streamed alongside
//  - softmax + alpha.V from smem
// ---------------------------------------------------------------------------
__global__ __launch_bounds__(256) void kb_fused_kernel(
    const float* __restrict__ Q,
    const float* __restrict__ K_kb,
    const float* __restrict__ V_kb,
    const float* __restrict__ ctx,
    const float* __restrict__ W_ctx,
    const float* __restrict__ b_ctx,
    const float* __restrict__ rel_emb,
    const float* __restrict__ ent_emb,
    const float* __restrict__ q_min,
    const float* __restrict__ q_max,
    const float* __restrict__ tau_min,
    const float* __restrict__ tau_max,
    const int*   __restrict__ rel_id,
    const int*   __restrict__ ent_id,
    float* __restrict__ out_alpha,
    float* __restrict__ out_v)
{
    extern __shared__ float smem[];
    float* sA    = smem;                         // [2][STAGE_F] stages
    float* sV    = smem + 2 * STAGE_F;           // [64][128]
    float* sQ    = sV + KCAND * DV;              // 128
    float* sQW   = sQ + DK;                      // 256
    float* sS    = sQW + DCTX;                   // 64 scores -> alpha
    int*   sRid  = (int*)(sS + KCAND);           // 64
    int*   sEid  = sRid + KCAND;                 // 64
    float* sTmin = (float*)(sEid + KCAND);       // 64
    float* sTmax = sTmin + KCAND;                // 64

    const int row  = blockIdx.x;
    const int tid  = threadIdx.x;
    const int warp = tid >> 5;
    const int lane = tid & 31;

    const long base_k = (long)row * KCAND * DK;
    const long base_c = (long)row * KCAND * DCTX;

    // ---- prologue: small per-row data ----
    if (tid < 64)        sRid [tid]       = rel_id [row * KCAND + tid];
    else if (tid < 128)  sEid [tid - 64]  = ent_id [row * KCAND + tid - 64];
    else if (tid < 192)  sTmin[tid - 128] = tau_min[row * KCAND + tid - 128];
    else                 sTmax[tid - 192] = tau_max[row * KCAND + tid - 192];
    if (tid < DK) sQ[tid] = Q[(long)row * DK + tid];
    __syncthreads();    // ids (for cp.async addresses) + sQ (for Qw) visible

    // ---- chunk issuer: K+ctx+rel+ent stage (20KB) + V slice (4KB), 1 group
    auto issue_chunk = [&](int c, int stg) {
        const int kc = c * CHUNK;
        const unsigned dst = smem_u32(sA + stg * STAGE_F);
        // K      f4 idx [0,256)
        { const int cand = tid >> 5, off = tid & 31;
          CP_ASYNC_CG16(dst + tid * 16,
                        K_kb + base_k + (long)(kc + cand) * DK + off * 4); }
        // ctx    f4 idx [256,768)
        { const int cand = tid >> 6, off = tid & 63;
          CP_ASYNC_CG16(dst + (256 + tid) * 16,
                        ctx + base_c + (long)(kc + cand) * DCTX + off * 4); }
        { const int t = tid + 256; const int cand = t >> 6, off = t & 63;
          CP_ASYNC_CG16(dst + (256 + t) * 16,
                        ctx + base_c + (long)(kc + cand) * DCTX + off * 4); }
        // rel    f4 idx [768,1024)
        { const int cand = tid >> 5, off = tid & 31;
          CP_ASYNC_CG16(dst + (768 + tid) * 16,
                        rel_emb + (long)sRid[kc + cand] * DK + off * 4); }
        // ent    f4 idx [1024,1280)
        { const int cand = tid >> 5, off = tid & 31;
          CP_ASYNC_CG16(dst + (1024 + tid) * 16,
                        ent_emb + (long)sEid[kc + cand] * DK + off * 4); }
        // V slice: rows kc..kc+7
        { const int cand = tid >> 5, off = tid & 31;
          CP_ASYNC_CG16(smem_u32(sV + (kc + cand) * DV + off * 4),
                        V_kb + base_k + (long)(kc + cand) * DV + off * 4); }
        CP_ASYNC_COMMIT();
    };

    issue_chunk(0, 0);
    issue_chunk(1, 1);

    // ---- fused Qw = Q_row @ W_ctx, overlapping in-flight copies ----
    // thread: column group cg (4 cols), d-partition part (32 d's each)
    {
        const int cg   = tid & 63;
        const int part = tid >> 6;
        const float4* W4 = (const float4*)W_ctx;   // [128][64] float4, L2-hot
        float4 acc = make_float4(0.f, 0.f, 0.f, 0.f);
#pragma unroll 8
        for (int i = 0; i < 32; ++i) {
            const int d = part * 32 + i;
            const float  qd = sQ[d];               // warp broadcast
            const float4 wv = W4[d * 64 + cg];     // coalesced, L2-hot
            acc.x = fmaf(qd, wv.x, acc.x); acc.y = fmaf(qd, wv.y, acc.y);
            acc.z = fmaf(qd, wv.z, acc.z); acc.w = fmaf(qd, wv.w, acc.w);
        }
        // scratch aliased on sV rows 32..39 (first cp.async write there is
        // chunk 4, issued only after the main loop starts)
        float4* tmp = (float4*)(sV + 32 * DV);     // [4][64] float4
        tmp[part * 64 + cg] = acc;
        __syncthreads();
        if (part == 0) {
            float4 r0 = tmp[cg], r1 = tmp[64 + cg],
                   r2 = tmp[128 + cg], r3 = tmp[192 + cg];
            float4 r = make_float4(r0.x + r1.x + r2.x + r3.x,
                                   r0.y + r1.y + r2.y + r3.y,
                                   r0.z + r1.z + r2.z + r3.z,
                                   r0.w + r1.w + r2.w + r3.w);
            ((float4*)sQW)[cg] = r;
        }
        __syncthreads();
    }

    // qb = Q . b_ctx
    const float4 qv  = ((const float4*)sQ)[lane];
    const float4 bv  = ((const float4*)b_ctx)[lane];
    float qb = qv.x * bv.x + qv.y * bv.y + qv.z * bv.z + qv.w * bv.w;
#pragma unroll
    for (int off = 16; off; off >>= 1) qb += __shfl_xor_sync(~0u, qb, off);

    const float qmn = q_min[row];
    const float qmx = q_max[row];
    const float inv_sqrt = 0.08838834764831843f; // 1/sqrt(128)
    const float4 qwa = ((const float4*)sQW)[lane];
    const float4 qwb = ((const float4*)sQW)[lane + 32];

#pragma unroll
    for (int c = 0; c < NCHUNK; ++c) {
        if (c < NCHUNK - 1) { CP_ASYNC_WAIT(1); } else { CP_ASYNC_WAIT(0); }
        __syncthreads();    // chunk c data visible to all threads

        const float* S = sA + (c & 1) * STAGE_F;
        const int k = c * CHUNK + warp;   // this warp's candidate

        const float4 kv = ((const float4*)S)[warp * 32 + lane];
        const float4 c0 = ((const float4*)(S + 1024))[warp * 64 + lane];
        const float4 c1 = ((const float4*)(S + 1024))[warp * 64 + lane + 32];
        const float4 rv = ((const float4*)(S + 3072))[warp * 32 + lane];
        const float4 ev = ((const float4*)(S + 4096))[warp * 32 + lane];

        float sem = qv.x * kv.x + qv.y * kv.y + qv.z * kv.z + qv.w * kv.w;
        float cx  = qv.x * (rv.x + ev.x) + qv.y * (rv.y + ev.y)
                  + qv.z * (rv.z + ev.z) + qv.w * (rv.w + ev.w);
        cx += qwa.x * c0.x + qwa.y * c0.y + qwa.z * c0.z + qwa.w * c0.w;
        cx += qwb.x * c1.x + qwb.y * c1.y + qwb.z * c1.z + qwb.w * c1.w;

        float tot = sem + GAMMA * cx;
#pragma unroll
        for (int off = 16; off; off >>= 1) tot += __shfl_xor_sync(~0u, tot, off);

        if (lane == 0) {
            const float tmin = sTmin[k];
            const float tmax = sTmax[k];
            const float inter = fmaxf(fminf(qmx, tmax) - fmaxf(qmn, tmin), 0.f);
            const float uni   = fmaxf(qmx, tmax) - fminf(qmn, tmin);
            const float ts    = inter / (uni + 1e-6f);
            sS[k] = (tot + GAMMA * qb) * inv_sqrt + ETA * ts;
        }
        __syncthreads();    // compute done before buffer reuse
        if (c + 2 < NCHUNK) issue_chunk(c + 2, c & 1);
    }

    // Softmax over 64 scores (warp 0)
    if (warp == 0) {
        float s0 = sS[lane], s1 = sS[lane + 32];
        float m = fmaxf(s0, s1);
#pragma unroll
        for (int off = 16; off; off >>= 1) m = fmaxf(m, __shfl_xor_sync(~0u, m, off));
        float e0 = __expf((s0 - m) * INV_TEMP);
        float e1 = __expf((s1 - m) * INV_TEMP);
        float sum = e0 + e1;
#pragma unroll
        for (int off = 16; off; off >>= 1) sum += __shfl_xor_sync(~0u, sum, off);
        const float inv = 1.0f / sum;
        const float a0 = e0 * inv, a1 = e1 * inv;
        sS[lane]      = a0;
        sS[lane + 32] = a1;
        out_alpha[row * KCAND + lane]      = a0;
        out_alpha[row * KCAND + lane + 32] = a1;
    }
    __syncthreads();

    // V_tilde = sum_k alpha[k] * V[k,:] from smem — split k across 2 groups
    const int g = tid >> 7;
    const int d = tid & 127;
    const float* vs = sV + g * 32 * DV;
    float acc = 0.f;
#pragma unroll
    for (int kk = 0; kk < 32; ++kk)
        acc = fmaf(sS[g * 32 + kk], vs[kk * DV + d], acc);
    float* sVp = sQW;   // reuse (Qw already consumed into registers)
    if (g) sVp[d] = acc;
    __syncthreads();
    if (!g) out_v[(long)row * DV + d] = acc + sVp[d];
}

// ---------------------------------------------------------------------------
extern "C" void kernel_launch(void* const* d_in, const int* in_sizes, int n_in,
                              void* d_out, int out_size) {
    const float* Q     = (const float*)d_in[0];
    const float* K_kb  = (const float*)d_in[1];
    const float* V_kb  = (const float*)d_in[2];
    const float* ctx   = (const float*)d_in[3];
    const float* W     = (const float*)d_in[4];
    const float* b_ctx = (const float*)d_in[5];
    const float* rel   = (const float*)d_in[6];
    const float* ent   = (const float*)d_in[7];
    const float* qmin  = (const float*)d_in[8];
    const float* qmax  = (const float*)d_in[9];
    const float* tmin  = (const float*)d_in[10];
    const float* tmax  = (const float*)d_in[11];
    const int*   rid   = (const int*)d_in[12];
    const int*   eid   = (const int*)d_in[13];

    float* out       = (float*)d_out;
    float* out_alpha = out;                    // [BT, 64]
    float* out_v     = out + BT * KCAND;       // [BT, 128]

    cudaFuncSetAttribute(kb_fused_kernel,
                         cudaFuncAttributeMaxDynamicSharedMemorySize,
                         SMEM_BYTES);

    kb_fused_kernel<<<BT, 256, SMEM_BYTES>>>(Q, K_kb, V_kb, ctx, W, b_ctx,
                                             rel, ent, qmin, qmax, tmin, tmax,
                                             rid, eid, out_alpha, out_v);
}